// round 5
// baseline (speedup 1.0000x reference)
#include <cuda_runtime.h>

#define BSZ 4
#define UE  8
#define RX  128
#define DD  64
#define NBU 32

// Scratch
__device__ float g_P[NBU*RX*DD];
__device__ float g_B[NBU*RX*DD];
__device__ float g_G[NBU*RX*DD];
__device__ float g_S[NBU*RX*RX];       // <P_i, B_j> per bu
__device__ float g_stats[NBU*RX*8];    // sumP,sumP2,sumB,sumB2,sumG,sumG2,sPG,sBG

typedef unsigned long long u64;

__device__ __forceinline__ u64 packf2(float lo, float hi) {
    u64 r; asm("mov.b64 %0, {%1, %2};" : "=l"(r) : "f"(lo), "f"(hi)); return r;
}
__device__ __forceinline__ u64 ffma2(u64 a, u64 b, u64 c) {
    u64 d; asm("fma.rn.f32x2 %0, %1, %2, %3;" : "=l"(d) : "l"(a), "l"(b), "l"(c)); return d;
}
__device__ __forceinline__ u64 fadd2(u64 a, u64 b) {
    u64 d; asm("add.rn.f32x2 %0, %1, %2;" : "=l"(d) : "l"(a), "l"(b)); return d;
}

// -------------------------------------------------------------------------
// Kernel 1: P,B,G rows + per-row moment stats.
// grid = (NBU, 16), 256 threads; CTA handles 8 i-rows of one bu.
// -------------------------------------------------------------------------
__global__ void __launch_bounds__(256) prep_kernel(
    const float* __restrict__ x,   // [NBU, RX, DD]
    const float* __restrict__ W1,  // [DD, 5*DD]
    const float* __restrict__ b1)  // [DD]
{
    const int bu  = blockIdx.x;
    const int ic0 = blockIdx.y * 8;

    __shared__ float xs[RX*65];
    __shared__ float msp[4][DD];
    __shared__ float ms[DD];
    __shared__ float sPm[8][DD], sBm[8][DD], sGm[8][DD];

    const float* xp = x + (size_t)bu * RX * DD;
    for (int t = threadIdx.x; t < RX*DD; t += 256) {
        int r = t >> 6, c = t & 63;
        xs[r*65 + c] = xp[t];
    }
    __syncthreads();

    {
        const int col = threadIdx.x & 63;
        const int qr  = threadIdx.x >> 6;
        float s = 0.f;
        #pragma unroll 8
        for (int r = qr*32; r < qr*32 + 32; r++) s += xs[r*65 + col];
        msp[qr][col] = s;
    }
    __syncthreads();
    if (threadIdx.x < DD) {
        ms[threadIdx.x] = (msp[0][threadIdx.x] + msp[1][threadIdx.x] +
                           msp[2][threadIdx.x] + msp[3][threadIdx.x]) * (1.f / RX);
    }
    __syncthreads();

    // 8 i * 64 o = 512 tasks
    for (int idx = threadIdx.x; idx < 8*DD; idx += 256) {
        const int il = idx & 7;
        const int i  = ic0 + il;
        const int o  = idx >> 3;
        const float* w  = W1 + o * (5*DD);
        const float* xi = xs + i * 65;
        float accP = b1[o], accB = 0.f, accG = 0.f;
        #pragma unroll 8
        for (int k = 0; k < DD; k++) {
            const float xv = xi[k];
            const float mv = ms[k];
            accG += xv * w[k];
            accP += xv * w[DD   + k];
            accB += xv * w[2*DD + k];
            accG += mv * w[3*DD + k];
            accP += mv * w[4*DD + k];
        }
        const int off = (bu*RX + i)*DD + o;
        g_P[off] = accP;
        g_B[off] = accB;
        g_G[off] = accG;
        sPm[il][o] = accP;
        sBm[il][o] = accB;
        sGm[il][o] = accG;
    }
    __syncthreads();

    // warp w reduces moments for row ic0+w
    const int w    = threadIdx.x >> 5;
    const int lane = threadIdx.x & 31;
    {
        const float p0 = sPm[w][lane], p1 = sPm[w][lane+32];
        const float b0 = sBm[w][lane], b1v = sBm[w][lane+32];
        const float g0 = sGm[w][lane], g1 = sGm[w][lane+32];
        float v0 = p0 + p1;
        float v1 = p0*p0 + p1*p1;
        float v2 = b0 + b1v;
        float v3 = b0*b0 + b1v*b1v;
        float v4 = g0 + g1;
        float v5 = g0*g0 + g1*g1;
        float v6 = p0*g0 + p1*g1;
        float v7 = b0*g0 + b1v*g1;
        #pragma unroll
        for (int m = 16; m > 0; m >>= 1) {
            v0 += __shfl_xor_sync(0xffffffffu, v0, m);
            v1 += __shfl_xor_sync(0xffffffffu, v1, m);
            v2 += __shfl_xor_sync(0xffffffffu, v2, m);
            v3 += __shfl_xor_sync(0xffffffffu, v3, m);
            v4 += __shfl_xor_sync(0xffffffffu, v4, m);
            v5 += __shfl_xor_sync(0xffffffffu, v5, m);
            v6 += __shfl_xor_sync(0xffffffffu, v6, m);
            v7 += __shfl_xor_sync(0xffffffffu, v7, m);
        }
        if (lane == 0) {
            float* s = g_stats + (size_t)(bu*RX + ic0 + w)*8;
            s[0]=v0; s[1]=v1; s[2]=v2; s[3]=v3; s[4]=v4; s[5]=v5; s[6]=v6; s[7]=v7;
        }
    }
}

// -------------------------------------------------------------------------
// Kernel 2: S[bu][i][j] = <P_i, B_j>.
// grid = (NBU, 4), 256 threads; CTA: 32 i-rows x all 128 j.
// -------------------------------------------------------------------------
__global__ void __launch_bounds__(256) spb_kernel()
{
    const int bu  = blockIdx.x;
    const int ic0 = blockIdx.y * 32;

    __shared__ float Ps[32*65];
    __shared__ float Bs[RX*65];

    const float* Pb = g_P + (size_t)(bu*RX + ic0)*DD;
    for (int t = threadIdx.x; t < 32*DD; t += 256) {
        int r = t >> 6, c = t & 63;
        Ps[r*65 + c] = Pb[t];
    }
    const float* Bb = g_B + (size_t)bu*RX*DD;
    for (int t = threadIdx.x; t < RX*DD; t += 256) {
        int r = t >> 6, c = t & 63;
        Bs[r*65 + c] = Bb[t];
    }
    __syncthreads();

    const int il = threadIdx.x & 31;          // i within block
    const int jb = threadIdx.x >> 5;          // warp -> 16-j chunk
    const float* pr = Ps + il*65;
    float* so = g_S + ((size_t)(bu*RX) + ic0 + il)*RX + jb*16;
    #pragma unroll 1
    for (int jo = 0; jo < 16; jo++) {
        const float* br = Bs + (jb*16 + jo)*65;
        float a0 = 0.f, a1 = 0.f;
        #pragma unroll 8
        for (int k = 0; k < DD; k += 2) {
            a0 += pr[k]   * br[k];
            a1 += pr[k+1] * br[k+1];
        }
        so[jo] = a0 + a1;
    }
}

// -------------------------------------------------------------------------
// Kernel 3: per cell (i,j): closed-form LN stats -> relu -> fc2.
// grid = (RX, NBU), 128 threads; lane owns o = 2*lane, 2*lane+1.
// No shuffles. Matvec via smem splat + FFMA2.
// -------------------------------------------------------------------------
__global__ void __launch_bounds__(128, 3) main_kernel(
    const float* __restrict__ ln_g, const float* __restrict__ ln_b,
    const float* __restrict__ bias, const float* __restrict__ W2,
    const float* __restrict__ b2,   float* __restrict__ out)
{
    const int i    = blockIdx.x;
    const int bu   = blockIdx.y;
    const int warp = threadIdx.x >> 5;
    const int lane = threadIdx.x & 31;
    const int o0   = 2*lane;

    __shared__ __align__(16) u64 ys[4][2][DD];   // 4KB

    // W2 rows o0, o0+1 packed as f32x2 pairs: w2p[k] = (W2[o0][k], W2[o0+1][k])
    u64 w2p[DD];
    {
        const float4* ra = (const float4*)(W2 + (size_t)o0 * DD);
        const float4* rb = ra + DD/4;
        #pragma unroll
        for (int q = 0; q < DD/4; q++) {
            float4 va = ra[q], vb = rb[q];
            w2p[4*q+0] = packf2(va.x, vb.x);
            w2p[4*q+1] = packf2(va.y, vb.y);
            w2p[4*q+2] = packf2(va.z, vb.z);
            w2p[4*q+3] = packf2(va.w, vb.w);
        }
    }
    const float g0  = ln_g[o0], g1  = ln_g[o0+1];
    const float lb0 = ln_b[o0], lb1 = ln_b[o0+1];
    const u64 b2p = packf2(b2[o0], b2[o0+1]);

    const size_t rowoff = (size_t)(bu*RX + i);
    const float2 pv = *(const float2*)(g_P + rowoff*DD + o0);
    const float2 gv = *(const float2*)(g_G + rowoff*DD + o0);
    const float* st    = g_stats + (size_t)(bu*RX)*8;
    const float2 sp    = *(const float2*)(st + i*8);        // sumP, sumP2
    const float* Bbase = g_B + (size_t)bu*RX*DD;
    const float* Srow  = g_S + rowoff*RX;
    float* obase = out + rowoff*RX*DD;

    // prefetch first j
    float2 bv = *(const float2*)(Bbase + warp*DD + o0);
    float2 sb = *(const float2*)(st + warp*8 + 2);          // sumB, sumB2
    float  sv = Srow[warp];

    #pragma unroll 1
    for (int jj = 0; jj < RX/4; jj++) {
        const int j = warp + jj*4;
        const float2 curB = bv;
        const float2 curSB = sb;
        const float  curS = sv;
        if (jj < RX/4 - 1) {
            const int jn = j + 4;
            bv = *(const float2*)(Bbase + jn*DD + o0);
            sb = *(const float2*)(st + jn*8 + 2);
            sv = Srow[jn];
        }

        float h0 = pv.x + curB.x;
        float h1 = pv.y + curB.y;
        float sumH = sp.x + curSB.x;
        float e2   = sp.y + curSB.y + 2.f*curS;
        if (j == i) {
            h0 += gv.x; h1 += gv.y;
            const float* sd = st + i*8;
            sumH += sd[4];
            e2   += sd[5] + 2.f*(sd[6] + sd[7]);
        }
        const float mu   = sumH * (1.f/64.f);
        const float var  = e2 * (1.f/64.f) - mu*mu;
        const float rstd = rsqrtf(var + 1e-5f);

        float y0 = fmaxf((h0 - mu) * rstd * g0 + lb0, 0.f);
        float y1 = fmaxf((h1 - mu) * rstd * g1 + lb1, 0.f);
        if (j == i) { y0 += bias[o0]; y1 += bias[o0+1]; }

        const int buf = jj & 1;
        *(float4*)&ys[warp][buf][o0] = make_float4(y0, y0, y1, y1);
        __syncwarp();

        const ulonglong2* yv = (const ulonglong2*)ys[warp][buf];
        u64 a0 = b2p, a1 = 0ull, a2 = 0ull, a3 = 0ull;
        #pragma unroll
        for (int k4 = 0; k4 < DD/4; k4++) {
            ulonglong2 q0 = yv[2*k4];
            ulonglong2 q1 = yv[2*k4+1];
            a0 = ffma2(w2p[4*k4+0], q0.x, a0);
            a1 = ffma2(w2p[4*k4+1], q0.y, a1);
            a2 = ffma2(w2p[4*k4+2], q1.x, a2);
            a3 = ffma2(w2p[4*k4+3], q1.y, a3);
        }
        const u64 acc = fadd2(fadd2(a0, a2), fadd2(a1, a3));
        *(u64*)(obase + (size_t)j*DD + o0) = acc;
    }
}

// -------------------------------------------------------------------------
// Inputs (metadata order): x, W1, b1, ln_g, ln_b, bias, W2, b2
// -------------------------------------------------------------------------
extern "C" void kernel_launch(void* const* d_in, const int* in_sizes, int n_in,
                              void* d_out, int out_size)
{
    const float* x    = (const float*)d_in[0];
    const float* W1   = (const float*)d_in[1];
    const float* b1   = (const float*)d_in[2];
    const float* ln_g = (const float*)d_in[3];
    const float* ln_b = (const float*)d_in[4];
    const float* bias = (const float*)d_in[5];
    const float* W2   = (const float*)d_in[6];
    const float* b2   = (const float*)d_in[7];
    float* out = (float*)d_out;
    (void)in_sizes; (void)n_in; (void)out_size;

    prep_kernel<<<dim3(NBU, 16), 256>>>(x, W1, b1);
    spb_kernel<<<dim3(NBU, 4), 256>>>();
    main_kernel<<<dim3(RX, NBU), 128>>>(ln_g, ln_b, bias, W2, b2, out);
}

// round 7
// speedup vs baseline: 1.5890x; 1.5890x over previous
#include <cuda_runtime.h>
#include <cuda_bf16.h>

#define RX   128
#define DD   64
#define NBU  32
#define NTILE (NBU*RX)   // 4096

// Scratch
__device__ float g_P[NBU*RX*DD];
__device__ float g_B[NBU*RX*DD];
__device__ float g_G[NBU*RX*DD];
__device__ float g_S[NBU*RX*RX];       // <P_i,B_j>
__device__ float g_stats[NBU*RX*8];    // sumP,sumP2,sumB,sumB2,sumG,sumG2,sPG,sBG

typedef unsigned int u32;

__device__ __forceinline__ u32 smem_u32(const void* p) {
    u32 a;
    asm("{ .reg .u64 t; cvta.to.shared.u64 t, %1; cvt.u32.u64 %0, t; }" : "=r"(a) : "l"(p));
    return a;
}

// -------------------------------------------------------------------------
// Kernel 1: P,B,G rows + per-row moment stats (o uniform per warp -> W1
// loads broadcast). grid = (NBU, 4), 256 threads.
// -------------------------------------------------------------------------
__global__ void __launch_bounds__(256) prep_kernel(
    const float* __restrict__ x,   // [NBU, RX, DD]
    const float* __restrict__ W1,  // [DD, 5*DD]
    const float* __restrict__ b1)
{
    const int bu  = blockIdx.x;
    const int ic0 = blockIdx.y * 32;
    const int t   = threadIdx.x;
    const int wid = t >> 5, lane = t & 31;

    __shared__ float xs[32*65];
    __shared__ float msp[4][DD];
    __shared__ float ms[DD];
    __shared__ float sP[32][DD], sB[32][DD], sG[32][DD];

    const float* xp = x + (size_t)bu * RX * DD;
    for (int tt = t; tt < 32*DD; tt += 256) {
        int r = tt >> 6, c = tt & 63;
        xs[r*65 + c] = xp[(size_t)(ic0 + r)*DD + c];
    }
    {   // mean over all 128 rows
        const int col = t & 63;
        const int q   = t >> 6;
        float s = 0.f;
        #pragma unroll 8
        for (int r = q*32; r < q*32 + 32; r++) s += xp[(size_t)r*DD + col];
        msp[q][col] = s;
    }
    __syncthreads();
    if (t < DD)
        ms[t] = (msp[0][t] + msp[1][t] + msp[2][t] + msp[3][t]) * (1.f / RX);
    __syncthreads();

    for (int idx = t; idx < 32*DD; idx += 256) {
        const int il = idx & 31;
        const int o  = idx >> 5;
        const float* w  = W1 + o * (5*DD);
        const float* xi = xs + il * 65;
        float accP = b1[o], accB = 0.f, accG = 0.f;
        #pragma unroll 8
        for (int k = 0; k < DD; k++) {
            const float xv = xi[k];
            const float mv = ms[k];
            accG += xv * w[k];
            accP += xv * w[DD   + k];
            accB += xv * w[2*DD + k];
            accG += mv * w[3*DD + k];
            accP += mv * w[4*DD + k];
        }
        const int off = (bu*RX + ic0 + il)*DD + o;
        g_P[off] = accP;
        g_B[off] = accB;
        g_G[off] = accG;
        sP[il][o] = accP;
        sB[il][o] = accB;
        sG[il][o] = accG;
    }
    __syncthreads();

    for (int r = 0; r < 4; r++) {
        const int row = wid*4 + r;
        const float p0 = sP[row][lane], p1 = sP[row][lane+32];
        const float b0 = sB[row][lane], b1v = sB[row][lane+32];
        const float q0 = sG[row][lane], q1 = sG[row][lane+32];
        float v0 = p0 + p1;
        float v1 = p0*p0 + p1*p1;
        float v2 = b0 + b1v;
        float v3 = b0*b0 + b1v*b1v;
        float v4 = q0 + q1;
        float v5 = q0*q0 + q1*q1;
        float v6 = p0*q0 + p1*q1;
        float v7 = b0*q0 + b1v*q1;
        #pragma unroll
        for (int m = 16; m > 0; m >>= 1) {
            v0 += __shfl_xor_sync(0xffffffffu, v0, m);
            v1 += __shfl_xor_sync(0xffffffffu, v1, m);
            v2 += __shfl_xor_sync(0xffffffffu, v2, m);
            v3 += __shfl_xor_sync(0xffffffffu, v3, m);
            v4 += __shfl_xor_sync(0xffffffffu, v4, m);
            v5 += __shfl_xor_sync(0xffffffffu, v5, m);
            v6 += __shfl_xor_sync(0xffffffffu, v6, m);
            v7 += __shfl_xor_sync(0xffffffffu, v7, m);
        }
        if (lane == 0) {
            float* s = g_stats + (size_t)(bu*RX + ic0 + row)*8;
            s[0]=v0; s[1]=v1; s[2]=v2; s[3]=v3; s[4]=v4; s[5]=v5; s[6]=v6; s[7]=v7;
        }
    }
}

// -------------------------------------------------------------------------
// Kernel 2: S[bu][i][j] = <P_i, B_j>. grid = (NBU, 4), 256 threads.
// -------------------------------------------------------------------------
__global__ void __launch_bounds__(256) spb_kernel()
{
    const int bu  = blockIdx.x;
    const int ic0 = blockIdx.y * 32;

    __shared__ float Ps[32*65];
    __shared__ float Bs[RX*65];

    const float* Pb = g_P + (size_t)(bu*RX + ic0)*DD;
    for (int t = threadIdx.x; t < 32*DD; t += 256) {
        int r = t >> 6, c = t & 63;
        Ps[r*65 + c] = Pb[t];
    }
    const float* Bb = g_B + (size_t)bu*RX*DD;
    for (int t = threadIdx.x; t < RX*DD; t += 256) {
        int r = t >> 6, c = t & 63;
        Bs[r*65 + c] = Bb[t];
    }
    __syncthreads();

    const int il = threadIdx.x & 31;
    const int jb = threadIdx.x >> 5;
    const float* pr = Ps + il*65;
    float* so = g_S + ((size_t)(bu*RX) + ic0 + il)*RX + jb*16;
    #pragma unroll 1
    for (int jo = 0; jo < 16; jo++) {
        const float* br = Bs + (jb*16 + jo)*65;
        float a0 = 0.f, a1 = 0.f;
        #pragma unroll 8
        for (int k = 0; k < DD; k += 2) {
            a0 += pr[k]   * br[k];
            a1 += pr[k+1] * br[k+1];
        }
        so[jo] = a0 + a1;
    }
}

// -------------------------------------------------------------------------
// Kernel 3: HMMA main. Persistent CTAs, 256 thr. Per tile (bu,i):
// warp w produces Y rows 16w..16w+15 (closed-form LN), bf16 hi/lo split,
// then consumes ONLY its own rows: ldmatrix A frags + mma.sync m16n8k16
// (3-pass error split), epilogue +b2, STG. No __syncthreads in the loop.
// -------------------------------------------------------------------------
// dynamic smem layout (bytes):
#define SM_B2   0                       // 64 f32          = 256
#define SM_BHI  256                     // [4][8][32] uint2 = 8192
#define SM_BLO  (256 + 8192)            // 8192
#define SM_AHI  (256 + 16384)           // 128 rows x 72 bf16 = 18432
#define SM_ALO  (256 + 16384 + 18432)   // 18432
#define SM_TOTAL (256 + 16384 + 36864)  // 53504
#define ASTRIDE 144                     // bytes per A row (72 bf16)

__device__ __forceinline__ void mma_bf16(
    float &c0, float &c1, float &c2, float &c3,
    u32 a0, u32 a1, u32 a2, u32 a3, u32 b0, u32 b1)
{
    asm volatile(
        "mma.sync.aligned.m16n8k16.row.col.f32.bf16.bf16.f32 "
        "{%0,%1,%2,%3}, {%4,%5,%6,%7}, {%8,%9}, {%0,%1,%2,%3};"
        : "+f"(c0), "+f"(c1), "+f"(c2), "+f"(c3)
        : "r"(a0), "r"(a1), "r"(a2), "r"(a3), "r"(b0), "r"(b1));
}
__device__ __forceinline__ void ldmat4(u32 r[4], u32 addr) {
    asm volatile("ldmatrix.sync.aligned.m8n8.x4.shared.b16 {%0,%1,%2,%3}, [%4];"
        : "=r"(r[0]), "=r"(r[1]), "=r"(r[2]), "=r"(r[3]) : "r"(addr));
}
__device__ __forceinline__ u32 bf2_u32(float a, float b) {
    __nv_bfloat162 h = __floats2bfloat162_rn(a, b);
    return *(u32*)&h;
}

__global__ void __launch_bounds__(256) main_mma(
    const float* __restrict__ ln_g, const float* __restrict__ ln_b,
    const float* __restrict__ bias, const float* __restrict__ W2,
    const float* __restrict__ b2,   float* __restrict__ out)
{
    extern __shared__ char smem[];
    const u32 sb   = smem_u32(smem);
    const int t    = threadIdx.x;
    const int wid  = t >> 5;
    const int lane = t & 31;

    float* b2s  = (float*)(smem + SM_B2);
    uint2* Bhi  = (uint2*)(smem + SM_BHI);   // [ks][nt][lane]
    uint2* Blo  = (uint2*)(smem + SM_BLO);

    if (t < DD) b2s[t] = b2[t];

    // Prologue: B fragments from W2 (hi + residual lo).
    // slot s: lane_s = s&31, nt = (s>>5)&7, ks = s>>8
    for (int s = t; s < 4*8*32; s += 256) {
        const int ls = s & 31, nt = (s >> 5) & 7, ks = s >> 8;
        const int o  = nt*8 + (ls >> 2);
        const int d  = ks*16 + (ls & 3)*2;
        const float* w = W2 + (size_t)o*DD + d;
        float w0 = w[0], w1 = w[1], w8 = w[8], w9 = w[9];
        __nv_bfloat16 h0 = __float2bfloat16(w0), h1 = __float2bfloat16(w1);
        __nv_bfloat16 h8 = __float2bfloat16(w8), h9 = __float2bfloat16(w9);
        uint2 bh, bl;
        bh.x = ((u32)*(unsigned short*)&h0) | ((u32)*(unsigned short*)&h1 << 16);
        bh.y = ((u32)*(unsigned short*)&h8) | ((u32)*(unsigned short*)&h9 << 16);
        bl.x = bf2_u32(w0 - __bfloat162float(h0), w1 - __bfloat162float(h1));
        bl.y = bf2_u32(w8 - __bfloat162float(h8), w9 - __bfloat162float(h9));
        const int idx = (ks*8 + nt)*32 + ls;
        Bhi[idx] = bh;
        Blo[idx] = bl;
    }
    __syncthreads();

    // per-lane d-pair for the producer
    const int d0 = 2*lane;
    const float lg0 = ln_g[d0], lg1 = ln_g[d0+1];
    const float lbn0 = ln_b[d0], lbn1 = ln_b[d0+1];
    const float bi0 = bias[d0], bi1 = bias[d0+1];

    // ldmatrix source addresses for this thread (A frag, own m-tile)
    const int arow = wid*16 + (lane & 15);
    const u32 a_off = (u32)arow*ASTRIDE + (u32)(lane >> 4)*16;
    const u32 ahi_base = sb + SM_AHI + a_off;
    const u32 alo_base = sb + SM_ALO + a_off;

    const int g  = lane >> 2;    // D-frag row group
    const int t4 = lane & 3;     // D-frag col pair

    for (int tile = blockIdx.x; tile < NTILE; tile += gridDim.x) {
        const int bu = tile >> 7;
        const int i  = tile & 127;
        const size_t row = (size_t)bu*RX + i;
        const float* st  = g_stats + (size_t)bu*RX*8;

        const float2 P2  = *(const float2*)(g_P + row*DD + d0);
        const float2 G2  = *(const float2*)(g_G + row*DD + d0);
        const float2 spi = *(const float2*)(st + i*8);       // sumP, sumP2
        const float4 sdi = *(const float4*)(st + i*8 + 4);   // sumG,sumG2,sPG,sBG
        const float* Bb  = g_B + (size_t)bu*RX*DD;
        const float* Sr  = g_S + row*RX;

        // ---- producer: rows 16*wid .. +15, lane covers d0,d0+1 ----
        __syncwarp();
        #pragma unroll 1
        for (int jo = 0; jo < 16; jo++) {
            const int j = wid*16 + jo;
            const float2 B2v = *(const float2*)(Bb + (size_t)j*DD + d0);
            const float2 sbj = *(const float2*)(st + j*8 + 2);
            const float  Sij = Sr[j];
            float h0  = P2.x + B2v.x;
            float h1  = P2.y + B2v.y;
            float sum = spi.x + sbj.x;
            float e2  = spi.y + sbj.y + 2.f*Sij;
            const bool diag = (j == i);
            if (diag) {
                h0 += G2.x; h1 += G2.y;
                sum += sdi.x;
                e2  += sdi.y + 2.f*(sdi.z + sdi.w);
            }
            const float mu  = sum * (1.f/64.f);
            const float var = e2 * (1.f/64.f) - mu*mu;
            const float rs  = rsqrtf(var + 1e-5f);
            float y0 = fmaxf((h0 - mu)*rs*lg0 + lbn0, 0.f);
            float y1 = fmaxf((h1 - mu)*rs*lg1 + lbn1, 0.f);
            if (diag) { y0 += bi0; y1 += bi1; }

            __nv_bfloat16 hh0 = __float2bfloat16(y0);
            __nv_bfloat16 hh1 = __float2bfloat16(y1);
            u32 hiw = ((u32)*(unsigned short*)&hh0) | ((u32)*(unsigned short*)&hh1 << 16);
            u32 low = bf2_u32(y0 - __bfloat162float(hh0), y1 - __bfloat162float(hh1));
            const u32 boff = (u32)j*ASTRIDE + (u32)lane*4;
            *(u32*)(smem + SM_AHI + boff) = hiw;
            *(u32*)(smem + SM_ALO + boff) = low;
        }
        __syncwarp();

        // ---- A fragments (own rows only) ----
        u32 ah[4][4], al[4][4];
        #pragma unroll
        for (int ks = 0; ks < 4; ks++) {
            ldmat4(ah[ks], ahi_base + (u32)ks*32);
            ldmat4(al[ks], alo_base + (u32)ks*32);
        }
        __syncwarp();

        // ---- MMA + epilogue per n-tile ----
        float* obase = out + row*RX*DD;
        #pragma unroll
        for (int nt = 0; nt < 8; nt++) {
            float c0 = 0.f, c1 = 0.f, c2 = 0.f, c3 = 0.f;
            #pragma unroll
            for (int ks = 0; ks < 4; ks++) {
                const int idx = (ks*8 + nt)*32 + lane;
                uint2 bh = Bhi[idx];
                uint2 bl = Blo[idx];
                mma_bf16(c0,c1,c2,c3, ah[ks][0],ah[ks][1],ah[ks][2],ah[ks][3], bh.x, bh.y);
                mma_bf16(c0,c1,c2,c3, ah[ks][0],ah[ks][1],ah[ks][2],ah[ks][3], bl.x, bl.y);
                mma_bf16(c0,c1,c2,c3, al[ks][0],al[ks][1],al[ks][2],al[ks][3], bh.x, bh.y);
            }
            const int o0 = nt*8 + t4*2;
            const float2 bb = *(const float2*)(b2s + o0);
            float2 v0; v0.x = c0 + bb.x; v0.y = c1 + bb.y;
            float2 v1; v1.x = c2 + bb.x; v1.y = c3 + bb.y;
            *(float2*)(obase + (size_t)(wid*16 + g)*DD + o0)     = v0;
            *(float2*)(obase + (size_t)(wid*16 + g + 8)*DD + o0) = v1;
        }
    }
}

// -------------------------------------------------------------------------
// Inputs (metadata order): x, W1, b1, ln_g, ln_b, bias, W2, b2
// -------------------------------------------------------------------------
extern "C" void kernel_launch(void* const* d_in, const int* in_sizes, int n_in,
                              void* d_out, int out_size)
{
    const float* x    = (const float*)d_in[0];
    const float* W1   = (const float*)d_in[1];
    const float* b1   = (const float*)d_in[2];
    const float* ln_g = (const float*)d_in[3];
    const float* ln_b = (const float*)d_in[4];
    const float* bias = (const float*)d_in[5];
    const float* W2   = (const float*)d_in[6];
    const float* b2   = (const float*)d_in[7];
    float* out = (float*)d_out;
    (void)in_sizes; (void)n_in; (void)out_size;

    cudaFuncSetAttribute(main_mma, cudaFuncAttributeMaxDynamicSharedMemorySize, SM_TOTAL);

    prep_kernel<<<dim3(NBU, 4), 256>>>(x, W1, b1);
    spb_kernel<<<dim3(NBU, 4), 256>>>();
    main_mma<<<296, 256, SM_TOTAL>>>(ln_g, ln_b, bias, W2, b2, out);
}

// round 8
// speedup vs baseline: 3.1221x; 1.9648x over previous
#include <cuda_runtime.h>
#include <cuda_bf16.h>

#define RX   128
#define DD   64
#define NBU  32
#define NTILE (NBU*RX)   // 4096

// Scratch
__device__ float g_P[NBU*RX*DD];
__device__ float g_B[NBU*RX*DD];
__device__ float g_G[NBU*RX*DD];
__device__ float g_S[NBU*RX*RX];       // <P_i,B_j>
__device__ float g_stats[NBU*RX*8];    // sumP,sumP2,sumB,sumB2,sumG,sumG2,sPG,sBG

typedef unsigned int u32;

__device__ __forceinline__ u32 smem_u32(const void* p) {
    u32 a;
    asm("{ .reg .u64 t; cvta.to.shared.u64 t, %1; cvt.u32.u64 %0, t; }" : "=r"(a) : "l"(p));
    return a;
}

// -------------------------------------------------------------------------
// Kernel 1 (rewritten): P,B,G rows + per-row moment stats.
// grid = (NBU, 4), 512 threads, dynamic smem.
// Phase A: all 5 W1 blocks -> smem; mean m; pm = b1 + W1e@m, gm = W1d@m.
// Phase B: 3 float4 dots per (i,o), W1 via broadcast LDS.128.
// -------------------------------------------------------------------------
#define PREP_SMEM_FLOATS (5*4096 + 32*68 + 3*2048 + 8*64 + 3*64)
#define PREP_SMEM_BYTES  (PREP_SMEM_FLOATS*4)

__global__ void __launch_bounds__(512) prep_kernel(
    const float* __restrict__ x,   // [NBU, RX, DD]
    const float* __restrict__ W1,  // [DD, 5*DD]
    const float* __restrict__ b1)
{
    extern __shared__ float sm[];
    float* ws  = sm;                    // [5][64][64]
    float* xs  = ws + 5*4096;           // [32][68]
    float* sP  = xs + 32*68;            // [32][64]
    float* sB  = sP + 2048;
    float* sG  = sB + 2048;
    float* msp = sG + 2048;             // [8][64]
    float* mm  = msp + 512;             // [64]
    float* pm  = mm + 64;               // [64]
    float* gm  = pm + 64;               // [64]

    const int bu  = blockIdx.x;
    const int ic0 = blockIdx.y * 32;
    const int t   = threadIdx.x;
    const int wid = t >> 5, lane = t & 31;

    const float* xp = x + (size_t)bu * RX * DD;

    // W1 blocks -> smem (coalesced per block row)
    for (int idx = t; idx < 5*4096; idx += 512) {
        const int blk = idx >> 12;
        const int rem = idx & 4095;
        const int o = rem >> 6, k = rem & 63;
        ws[idx] = W1[(size_t)o*320 + blk*64 + k];
    }
    // own 32 x-rows -> smem (pitch 68)
    for (int idx = t; idx < 32*DD; idx += 512) {
        const int r = idx >> 6, c = idx & 63;
        xs[r*68 + c] = xp[(size_t)(ic0 + r)*DD + c];
    }
    // mean partials: 8 groups x 16 rows
    {
        const int col = t & 63;
        const int q   = t >> 6;
        float s = 0.f;
        #pragma unroll 4
        for (int r = q*16; r < q*16 + 16; r++) s += xp[(size_t)r*DD + col];
        msp[q*64 + col] = s;
    }
    __syncthreads();
    if (t < DD) {
        float s = 0.f;
        #pragma unroll
        for (int q = 0; q < 8; q++) s += msp[q*64 + t];
        mm[t] = s * (1.f / RX);
    }
    __syncthreads();

    // pm/gm: 8 threads per o, 8 k each, shfl-reduce within groups of 8
    {
        const int o  = t >> 3;
        const int kg = t & 7;
        float pv = 0.f, gv = 0.f;
        #pragma unroll
        for (int s = 0; s < 8; s++) {
            const int k = kg*8 + s;
            const float mv = mm[k];
            gv += ws[3*4096 + o*64 + k] * mv;
            pv += ws[4*4096 + o*64 + k] * mv;
        }
        #pragma unroll
        for (int m = 4; m > 0; m >>= 1) {
            pv += __shfl_xor_sync(0xffffffffu, pv, m);
            gv += __shfl_xor_sync(0xffffffffu, gv, m);
        }
        if (kg == 0) { pm[o] = b1[o] + pv; gm[o] = gv; }
    }
    __syncthreads();

    // Phase B: 2048 tasks, 4 per thread; o uniform per warp
    #pragma unroll
    for (int s = 0; s < 4; s++) {
        const int idx = t + s*512;
        const int il = idx & 31;
        const int o  = idx >> 5;
        const float4* xi = (const float4*)(xs + il*68);
        const float4* wa = (const float4*)(ws + 0*4096 + o*64);
        const float4* wb = (const float4*)(ws + 1*4096 + o*64);
        const float4* wc = (const float4*)(ws + 2*4096 + o*64);
        float accP = pm[o], accB = 0.f, accG = gm[o];
        #pragma unroll
        for (int k4 = 0; k4 < 16; k4++) {
            const float4 xv = xi[k4];
            const float4 a = wa[k4];
            const float4 b = wb[k4];
            const float4 c = wc[k4];
            accG += xv.x*a.x + xv.y*a.y + xv.z*a.z + xv.w*a.w;
            accP += xv.x*b.x + xv.y*b.y + xv.z*b.z + xv.w*b.w;
            accB += xv.x*c.x + xv.y*c.y + xv.z*c.z + xv.w*c.w;
        }
        const int off = (bu*RX + ic0 + il)*DD + o;
        g_P[off] = accP;
        g_B[off] = accB;
        g_G[off] = accG;
        sP[il*64 + o] = accP;
        sB[il*64 + o] = accB;
        sG[il*64 + o] = accG;
    }
    __syncthreads();

    // stats: 16 warps x 2 rows
    #pragma unroll
    for (int r = 0; r < 2; r++) {
        const int row = wid*2 + r;
        const float p0 = sP[row*64 + lane], p1 = sP[row*64 + lane+32];
        const float b0 = sB[row*64 + lane], b1v = sB[row*64 + lane+32];
        const float q0 = sG[row*64 + lane], q1 = sG[row*64 + lane+32];
        float v0 = p0 + p1;
        float v1 = p0*p0 + p1*p1;
        float v2 = b0 + b1v;
        float v3 = b0*b0 + b1v*b1v;
        float v4 = q0 + q1;
        float v5 = q0*q0 + q1*q1;
        float v6 = p0*q0 + p1*q1;
        float v7 = b0*q0 + b1v*q1;
        #pragma unroll
        for (int m = 16; m > 0; m >>= 1) {
            v0 += __shfl_xor_sync(0xffffffffu, v0, m);
            v1 += __shfl_xor_sync(0xffffffffu, v1, m);
            v2 += __shfl_xor_sync(0xffffffffu, v2, m);
            v3 += __shfl_xor_sync(0xffffffffu, v3, m);
            v4 += __shfl_xor_sync(0xffffffffu, v4, m);
            v5 += __shfl_xor_sync(0xffffffffu, v5, m);
            v6 += __shfl_xor_sync(0xffffffffu, v6, m);
            v7 += __shfl_xor_sync(0xffffffffu, v7, m);
        }
        if (lane == 0) {
            float* so = g_stats + (size_t)(bu*RX + ic0 + row)*8;
            so[0]=v0; so[1]=v1; so[2]=v2; so[3]=v3; so[4]=v4; so[5]=v5; so[6]=v6; so[7]=v7;
        }
    }
}

// -------------------------------------------------------------------------
// Kernel 2: S[bu][i][j] = <P_i, B_j>. grid = (NBU, 4), 256 threads.
// float4 inner loop (pitch 68).
// -------------------------------------------------------------------------
__global__ void __launch_bounds__(256) spb_kernel()
{
    const int bu  = blockIdx.x;
    const int ic0 = blockIdx.y * 32;

    __shared__ float Ps[32*68];
    __shared__ float Bs[RX*68];

    const float* Pb = g_P + (size_t)(bu*RX + ic0)*DD;
    for (int t = threadIdx.x; t < 32*DD; t += 256) {
        int r = t >> 6, c = t & 63;
        Ps[r*68 + c] = Pb[t];
    }
    const float* Bb = g_B + (size_t)bu*RX*DD;
    for (int t = threadIdx.x; t < RX*DD; t += 256) {
        int r = t >> 6, c = t & 63;
        Bs[r*68 + c] = Bb[t];
    }
    __syncthreads();

    const int il = threadIdx.x & 31;
    const int jb = threadIdx.x >> 5;
    const float4* pr = (const float4*)(Ps + il*68);
    float* so = g_S + ((size_t)(bu*RX) + ic0 + il)*RX + jb*16;
    #pragma unroll 1
    for (int jo = 0; jo < 16; jo++) {
        const float4* br = (const float4*)(Bs + (jb*16 + jo)*68);
        float a0 = 0.f, a1 = 0.f, a2 = 0.f, a3 = 0.f;
        #pragma unroll
        for (int k4 = 0; k4 < 16; k4++) {
            const float4 p = pr[k4];
            const float4 b = br[k4];
            a0 += p.x*b.x; a1 += p.y*b.y; a2 += p.z*b.z; a3 += p.w*b.w;
        }
        so[jo] = (a0 + a2) + (a1 + a3);
    }
}

// -------------------------------------------------------------------------
// Kernel 3: HMMA main. Persistent chunked CTAs, 256 thr, 3 CTAs/SM.
// Producer software-pipelined; warp-private m-tiles; no __syncthreads
// in the tile loop.
// -------------------------------------------------------------------------
#define SM_B2   0                       // 64 f32          = 256
#define SM_BHI  256                     // [4][8][32] uint2 = 8192
#define SM_BLO  (256 + 8192)            // 8192
#define SM_AHI  (256 + 16384)           // 128 rows x 72 bf16 = 18432
#define SM_ALO  (256 + 16384 + 18432)   // 18432
#define SM_TOTAL (256 + 16384 + 36864)  // 53504
#define ASTRIDE 144                     // bytes per A row (72 bf16)

__device__ __forceinline__ void mma_bf16(
    float &c0, float &c1, float &c2, float &c3,
    u32 a0, u32 a1, u32 a2, u32 a3, u32 b0, u32 b1)
{
    asm volatile(
        "mma.sync.aligned.m16n8k16.row.col.f32.bf16.bf16.f32 "
        "{%0,%1,%2,%3}, {%4,%5,%6,%7}, {%8,%9}, {%0,%1,%2,%3};"
        : "+f"(c0), "+f"(c1), "+f"(c2), "+f"(c3)
        : "r"(a0), "r"(a1), "r"(a2), "r"(a3), "r"(b0), "r"(b1));
}
__device__ __forceinline__ void ldmat4(u32 r[4], u32 addr) {
    asm volatile("ldmatrix.sync.aligned.m8n8.x4.shared.b16 {%0,%1,%2,%3}, [%4];"
        : "=r"(r[0]), "=r"(r[1]), "=r"(r[2]), "=r"(r[3]) : "r"(addr));
}
__device__ __forceinline__ u32 bf2_u32(float a, float b) {
    __nv_bfloat162 h = __floats2bfloat162_rn(a, b);
    return *(u32*)&h;
}

#define MAIN_GRID 444

__global__ void __launch_bounds__(256, 3) main_mma(
    const float* __restrict__ ln_g, const float* __restrict__ ln_b,
    const float* __restrict__ bias, const float* __restrict__ W2,
    const float* __restrict__ b2,   float* __restrict__ out)
{
    extern __shared__ char smem[];
    const u32 sb   = smem_u32(smem);
    const int t    = threadIdx.x;
    const int wid  = t >> 5;
    const int lane = t & 31;

    float* b2s  = (float*)(smem + SM_B2);
    uint2* Bhi  = (uint2*)(smem + SM_BHI);   // [ks][nt][lane]
    uint2* Blo  = (uint2*)(smem + SM_BLO);

    if (t < DD) b2s[t] = b2[t];

    // B fragments from W2 (hi + residual lo)
    for (int s = t; s < 4*8*32; s += 256) {
        const int ls = s & 31, nt = (s >> 5) & 7, ks = s >> 8;
        const int o  = nt*8 + (ls >> 2);
        const int d  = ks*16 + (ls & 3)*2;
        const float* w = W2 + (size_t)o*DD + d;
        float w0 = w[0], w1 = w[1], w8 = w[8], w9 = w[9];
        __nv_bfloat16 h0 = __float2bfloat16(w0), h1 = __float2bfloat16(w1);
        __nv_bfloat16 h8 = __float2bfloat16(w8), h9 = __float2bfloat16(w9);
        uint2 bh, bl;
        bh.x = ((u32)*(unsigned short*)&h0) | ((u32)*(unsigned short*)&h1 << 16);
        bh.y = ((u32)*(unsigned short*)&h8) | ((u32)*(unsigned short*)&h9 << 16);
        bl.x = bf2_u32(w0 - __bfloat162float(h0), w1 - __bfloat162float(h1));
        bl.y = bf2_u32(w8 - __bfloat162float(h8), w9 - __bfloat162float(h9));
        const int idx = (ks*8 + nt)*32 + ls;
        Bhi[idx] = bh;
        Blo[idx] = bl;
    }
    __syncthreads();

    const int d0 = 2*lane;
    const float lg0 = ln_g[d0], lg1 = ln_g[d0+1];
    const float lbn0 = ln_b[d0], lbn1 = ln_b[d0+1];
    const float bi0 = bias[d0], bi1 = bias[d0+1];

    const int arow = wid*16 + (lane & 15);
    const u32 a_off = (u32)arow*ASTRIDE + (u32)(lane >> 4)*16;
    const u32 ahi_base = sb + SM_AHI + a_off;
    const u32 alo_base = sb + SM_ALO + a_off;

    const int g  = lane >> 2;
    const int t4 = lane & 3;

    // chunked tile range: consecutive tiles share bu -> L2-hot B/stats/S
    const int per = (NTILE + MAIN_GRID - 1) / MAIN_GRID;     // 10
    const int tile0 = blockIdx.x * per;
    const int tile1 = (tile0 + per < NTILE) ? (tile0 + per) : NTILE;

    for (int tile = tile0; tile < tile1; tile++) {
        const int bu = tile >> 7;
        const int i  = tile & 127;
        const size_t row = (size_t)bu*RX + i;
        const float* st  = g_stats + (size_t)bu*RX*8;

        const float2 P2  = *(const float2*)(g_P + row*DD + d0);
        const float2 G2  = *(const float2*)(g_G + row*DD + d0);
        const float2 spi = *(const float2*)(st + i*8);
        const float4 sdi = *(const float4*)(st + i*8 + 4);
        const float* Bb  = g_B + (size_t)bu*RX*DD;
        const float* Sr  = g_S + row*RX;

        __syncwarp();
        // software-pipelined producer over own 16 rows
        float2 B2v = *(const float2*)(Bb + (size_t)(wid*16)*DD + d0);
        float2 sbj = *(const float2*)(st + (wid*16)*8 + 2);
        float  Sij = Sr[wid*16];
        #pragma unroll 1
        for (int jo = 0; jo < 16; jo++) {
            const int j = wid*16 + jo;
            const float2 cB = B2v;
            const float2 cS = sbj;
            const float  cs = Sij;
            if (jo < 15) {
                B2v = *(const float2*)(Bb + (size_t)(j+1)*DD + d0);
                sbj = *(const float2*)(st + (j+1)*8 + 2);
                Sij = Sr[j+1];
            }
            float h0  = P2.x + cB.x;
            float h1  = P2.y + cB.y;
            float sum = spi.x + cS.x;
            float e2  = spi.y + cS.y + 2.f*cs;
            const bool diag = (j == i);
            if (diag) {
                h0 += G2.x; h1 += G2.y;
                sum += sdi.x;
                e2  += sdi.y + 2.f*(sdi.z + sdi.w);
            }
            const float mu  = sum * (1.f/64.f);
            const float var = e2 * (1.f/64.f) - mu*mu;
            const float rs  = rsqrtf(var + 1e-5f);
            float y0 = fmaxf((h0 - mu)*rs*lg0 + lbn0, 0.f);
            float y1 = fmaxf((h1 - mu)*rs*lg1 + lbn1, 0.f);
            if (diag) { y0 += bi0; y1 += bi1; }

            __nv_bfloat16 hh0 = __float2bfloat16(y0);
            __nv_bfloat16 hh1 = __float2bfloat16(y1);
            u32 hiw = ((u32)*(unsigned short*)&hh0) | ((u32)*(unsigned short*)&hh1 << 16);
            u32 low = bf2_u32(y0 - __bfloat162float(hh0), y1 - __bfloat162float(hh1));
            const u32 boff = (u32)j*ASTRIDE + (u32)lane*4;
            *(u32*)(smem + SM_AHI + boff) = hiw;
            *(u32*)(smem + SM_ALO + boff) = low;
        }
        __syncwarp();

        u32 ah[4][4], al[4][4];
        #pragma unroll
        for (int ks = 0; ks < 4; ks++) {
            ldmat4(ah[ks], ahi_base + (u32)ks*32);
            ldmat4(al[ks], alo_base + (u32)ks*32);
        }
        __syncwarp();

        float* obase = out + row*RX*DD;
        #pragma unroll
        for (int nt = 0; nt < 8; nt++) {
            float c0 = 0.f, c1 = 0.f, c2 = 0.f, c3 = 0.f;
            #pragma unroll
            for (int ks = 0; ks < 4; ks++) {
                const int idx = (ks*8 + nt)*32 + lane;
                uint2 bh = Bhi[idx];
                uint2 bl = Blo[idx];
                mma_bf16(c0,c1,c2,c3, ah[ks][0],ah[ks][1],ah[ks][2],ah[ks][3], bh.x, bh.y);
                mma_bf16(c0,c1,c2,c3, ah[ks][0],ah[ks][1],ah[ks][2],ah[ks][3], bl.x, bl.y);
                mma_bf16(c0,c1,c2,c3, al[ks][0],al[ks][1],al[ks][2],al[ks][3], bh.x, bh.y);
            }
            const int o0 = nt*8 + t4*2;
            const float2 bb = *(const float2*)(b2s + o0);
            float2 v0; v0.x = c0 + bb.x; v0.y = c1 + bb.y;
            float2 v1; v1.x = c2 + bb.x; v1.y = c3 + bb.y;
            *(float2*)(obase + (size_t)(wid*16 + g)*DD + o0)     = v0;
            *(float2*)(obase + (size_t)(wid*16 + g + 8)*DD + o0) = v1;
        }
    }
}

// -------------------------------------------------------------------------
// Inputs (metadata order): x, W1, b1, ln_g, ln_b, bias, W2, b2
// -------------------------------------------------------------------------
extern "C" void kernel_launch(void* const* d_in, const int* in_sizes, int n_in,
                              void* d_out, int out_size)
{
    const float* x    = (const float*)d_in[0];
    const float* W1   = (const float*)d_in[1];
    const float* b1   = (const float*)d_in[2];
    const float* ln_g = (const float*)d_in[3];
    const float* ln_b = (const float*)d_in[4];
    const float* bias = (const float*)d_in[5];
    const float* W2   = (const float*)d_in[6];
    const float* b2   = (const float*)d_in[7];
    float* out = (float*)d_out;
    (void)in_sizes; (void)n_in; (void)out_size;

    cudaFuncSetAttribute(prep_kernel, cudaFuncAttributeMaxDynamicSharedMemorySize, PREP_SMEM_BYTES);
    cudaFuncSetAttribute(main_mma, cudaFuncAttributeMaxDynamicSharedMemorySize, SM_TOTAL);

    prep_kernel<<<dim3(NBU, 4), 512, PREP_SMEM_BYTES>>>(x, W1, b1);
    spb_kernel<<<dim3(NBU, 4), 256>>>();
    main_mma<<<MAIN_GRID, 256, SM_TOTAL>>>(ln_g, ln_b, bias, W2, b2, out);
}

// round 9
// speedup vs baseline: 3.5158x; 1.1261x over previous
#include <cuda_runtime.h>
#include <cuda_bf16.h>

#define RX   128
#define DD   64
#define NBU  32
#define NTILE (NBU*RX)   // 4096

// Scratch
__device__ float g_P[NBU*RX*DD];
__device__ float g_B[NBU*RX*DD];
__device__ float g_G[NBU*RX*DD];
__device__ float g_S[NBU*RX*RX];       // <P_i,B_j>
__device__ float g_stats[NBU*RX*8];    // sumP,sumP2,sumB,sumB2,sumG,sumG2,sPG,sBG
__device__ float g_pm[NBU*DD];         // b1 + W1[:,256:320]@m
__device__ float g_gm[NBU*DD];         // W1[:,192:256]@m

typedef unsigned int u32;

__device__ __forceinline__ u32 smem_u32(const void* p) {
    u32 a;
    asm("{ .reg .u64 t; cvta.to.shared.u64 t, %1; cvt.u32.u64 %0, t; }" : "=r"(a) : "l"(p));
    return a;
}

// -------------------------------------------------------------------------
// Kernel 0: per-bu mean + pm/gm (W1 blocks d,e folded with mean).
// grid = NBU, 256 threads.
// -------------------------------------------------------------------------
__global__ void __launch_bounds__(256) mean_kernel(
    const float* __restrict__ x, const float* __restrict__ W1,
    const float* __restrict__ b1)
{
    __shared__ float msp[4][DD];
    __shared__ float mm[DD];

    const int bu = blockIdx.x;
    const int t  = threadIdx.x;
    const float* xp = x + (size_t)bu * RX * DD;

    {
        const int col = t & 63;
        const int q   = t >> 6;
        float s = 0.f;
        #pragma unroll 8
        for (int r = q*32; r < q*32 + 32; r++) s += xp[(size_t)r*DD + col];
        msp[q][col] = s;
    }
    __syncthreads();
    if (t < DD)
        mm[t] = (msp[0][t] + msp[1][t] + msp[2][t] + msp[3][t]) * (1.f / RX);
    __syncthreads();

    const int o  = t >> 2;
    const int kq = t & 3;
    float pv = 0.f, gv = 0.f;
    #pragma unroll
    for (int s = 0; s < 16; s++) {
        const int k = kq*16 + s;
        const float mv = mm[k];
        gv += W1[(size_t)o*320 + 192 + k] * mv;
        pv += W1[(size_t)o*320 + 256 + k] * mv;
    }
    pv += __shfl_xor_sync(0xffffffffu, pv, 1);
    gv += __shfl_xor_sync(0xffffffffu, gv, 1);
    pv += __shfl_xor_sync(0xffffffffu, pv, 2);
    gv += __shfl_xor_sync(0xffffffffu, gv, 2);
    if (kq == 0) {
        g_pm[bu*DD + o] = b1[o] + pv;
        g_gm[bu*DD + o] = gv;
    }
}

// -------------------------------------------------------------------------
// Kernel 1: P,B,G rows + per-row stats. grid = (NBU, 8), 512 thr,
// 16 i-rows/CTA. Stages only W1 blocks a,b,c (48KB).
// -------------------------------------------------------------------------
#define PREP_SMEM_FLOATS (3*4096 + 16*68 + 3*16*65 + 2*64)
#define PREP_SMEM_BYTES  (PREP_SMEM_FLOATS*4)

__global__ void __launch_bounds__(512) prep_kernel(
    const float* __restrict__ x, const float* __restrict__ W1)
{
    extern __shared__ float sm[];
    float* ws  = sm;                    // [3][64][64]
    float* xs  = ws + 3*4096;           // [16][68]
    float* sP  = xs + 16*68;            // [16][65]
    float* sB  = sP + 16*65;
    float* sG  = sB + 16*65;
    float* pms = sG + 16*65;            // [64]
    float* gms = pms + 64;              // [64]

    const int bu  = blockIdx.x;
    const int ic0 = blockIdx.y * 16;
    const int t   = threadIdx.x;
    const int wid = t >> 5, lane = t & 31;

    const float* xp = x + (size_t)bu * RX * DD;

    // W1 blocks a,b,c -> smem (float4)
    for (int i4 = t; i4 < 3*1024; i4 += 512) {
        const int blk = i4 >> 10;
        const int rem = i4 & 1023;
        const int o = rem >> 4, k4 = rem & 15;
        const float4 v = *(const float4*)(W1 + (size_t)o*320 + blk*64 + k4*4);
        *(float4*)(ws + blk*4096 + o*64 + k4*4) = v;
    }
    // own 16 x-rows (float4, pitch 68)
    if (t < 256) {
        const int r = t >> 4, c4 = t & 15;
        const float4 v = *(const float4*)(xp + (size_t)(ic0 + r)*DD + c4*4);
        *(float4*)(xs + r*68 + c4*4) = v;
    }
    if (t >= 256 && t < 320) pms[t-256] = g_pm[bu*DD + (t-256)];
    if (t >= 320 && t < 384) gms[t-320] = g_gm[bu*DD + (t-320)];
    __syncthreads();

    // Phase B: 16 il x 64 o = 1024 tasks, 2/thread
    #pragma unroll
    for (int s = 0; s < 2; s++) {
        const int il = lane & 15;
        const int o  = wid*4 + (lane >> 4)*2 + s;
        const float4* xi = (const float4*)(xs + il*68);
        const float4* wa = (const float4*)(ws + 0*4096 + o*64);
        const float4* wb = (const float4*)(ws + 1*4096 + o*64);
        const float4* wc = (const float4*)(ws + 2*4096 + o*64);
        float accP = pms[o], accB = 0.f, accG = gms[o];
        #pragma unroll
        for (int k4 = 0; k4 < 16; k4++) {
            const float4 xv = xi[k4];
            const float4 a = wa[k4];
            const float4 b = wb[k4];
            const float4 c = wc[k4];
            accG += xv.x*a.x + xv.y*a.y + xv.z*a.z + xv.w*a.w;
            accP += xv.x*b.x + xv.y*b.y + xv.z*b.z + xv.w*b.w;
            accB += xv.x*c.x + xv.y*c.y + xv.z*c.z + xv.w*c.w;
        }
        const int off = (bu*RX + ic0 + il)*DD + o;
        g_P[off] = accP;
        g_B[off] = accB;
        g_G[off] = accG;
        sP[il*65 + o] = accP;
        sB[il*65 + o] = accB;
        sG[il*65 + o] = accG;
    }
    __syncthreads();

    // stats: 16 warps x 1 row
    {
        const int row = wid;
        const float p0 = sP[row*65 + lane], p1 = sP[row*65 + lane+32];
        const float b0 = sB[row*65 + lane], b1v = sB[row*65 + lane+32];
        const float q0 = sG[row*65 + lane], q1 = sG[row*65 + lane+32];
        float v0 = p0 + p1;
        float v1 = p0*p0 + p1*p1;
        float v2 = b0 + b1v;
        float v3 = b0*b0 + b1v*b1v;
        float v4 = q0 + q1;
        float v5 = q0*q0 + q1*q1;
        float v6 = p0*q0 + p1*q1;
        float v7 = b0*q0 + b1v*q1;
        #pragma unroll
        for (int m = 16; m > 0; m >>= 1) {
            v0 += __shfl_xor_sync(0xffffffffu, v0, m);
            v1 += __shfl_xor_sync(0xffffffffu, v1, m);
            v2 += __shfl_xor_sync(0xffffffffu, v2, m);
            v3 += __shfl_xor_sync(0xffffffffu, v3, m);
            v4 += __shfl_xor_sync(0xffffffffu, v4, m);
            v5 += __shfl_xor_sync(0xffffffffu, v5, m);
            v6 += __shfl_xor_sync(0xffffffffu, v6, m);
            v7 += __shfl_xor_sync(0xffffffffu, v7, m);
        }
        if (lane == 0) {
            float* so = g_stats + (size_t)(bu*RX + ic0 + row)*8;
            so[0]=v0; so[1]=v1; so[2]=v2; so[3]=v3; so[4]=v4; so[5]=v5; so[6]=v6; so[7]=v7;
        }
    }
}

// -------------------------------------------------------------------------
// Kernel 2: S[bu][i][j] = <P_i, B_j>. grid = (NBU, 4), 256 threads.
// -------------------------------------------------------------------------
__global__ void __launch_bounds__(256) spb_kernel()
{
    const int bu  = blockIdx.x;
    const int ic0 = blockIdx.y * 32;

    __shared__ float Ps[32*68];
    __shared__ float Bs[RX*68];

    const float* Pb = g_P + (size_t)(bu*RX + ic0)*DD;
    for (int t = threadIdx.x; t < 32*DD; t += 256) {
        int r = t >> 6, c = t & 63;
        Ps[r*68 + c] = Pb[t];
    }
    const float* Bb = g_B + (size_t)bu*RX*DD;
    for (int t = threadIdx.x; t < RX*DD; t += 256) {
        int r = t >> 6, c = t & 63;
        Bs[r*68 + c] = Bb[t];
    }
    __syncthreads();

    const int il = threadIdx.x & 31;
    const int jb = threadIdx.x >> 5;
    const float4* pr = (const float4*)(Ps + il*68);
    float* so = g_S + ((size_t)(bu*RX) + ic0 + il)*RX + jb*16;
    #pragma unroll 1
    for (int jo = 0; jo < 16; jo++) {
        const float4* br = (const float4*)(Bs + (jb*16 + jo)*68);
        float a0 = 0.f, a1 = 0.f, a2 = 0.f, a3 = 0.f;
        #pragma unroll
        for (int k4 = 0; k4 < 16; k4++) {
            const float4 p = pr[k4];
            const float4 b = br[k4];
            a0 += p.x*b.x; a1 += p.y*b.y; a2 += p.z*b.z; a3 += p.w*b.w;
        }
        so[jo] = (a0 + a2) + (a1 + a3);
    }
}

// -------------------------------------------------------------------------
// Kernel 3: HMMA main. B rows + stats hoisted per-bu into registers
// (lane-distributed, shfl broadcast). 2 CTAs/SM, chunked tiles.
// -------------------------------------------------------------------------
#define SM_B2   0
#define SM_BHI  256
#define SM_BLO  (256 + 8192)
#define SM_AHI  (256 + 16384)
#define SM_ALO  (256 + 16384 + 18432)
#define SM_TOTAL (256 + 16384 + 36864)  // 53504
#define ASTRIDE 144

__device__ __forceinline__ void mma_bf16(
    float &c0, float &c1, float &c2, float &c3,
    u32 a0, u32 a1, u32 a2, u32 a3, u32 b0, u32 b1)
{
    asm volatile(
        "mma.sync.aligned.m16n8k16.row.col.f32.bf16.bf16.f32 "
        "{%0,%1,%2,%3}, {%4,%5,%6,%7}, {%8,%9}, {%0,%1,%2,%3};"
        : "+f"(c0), "+f"(c1), "+f"(c2), "+f"(c3)
        : "r"(a0), "r"(a1), "r"(a2), "r"(a3), "r"(b0), "r"(b1));
}
__device__ __forceinline__ void ldmat4(u32 r[4], u32 addr) {
    asm volatile("ldmatrix.sync.aligned.m8n8.x4.shared.b16 {%0,%1,%2,%3}, [%4];"
        : "=r"(r[0]), "=r"(r[1]), "=r"(r[2]), "=r"(r[3]) : "r"(addr));
}
__device__ __forceinline__ u32 bf2_u32(float a, float b) {
    __nv_bfloat162 h = __floats2bfloat162_rn(a, b);
    return *(u32*)&h;
}

#define MAIN_PER  14
#define MAIN_GRID ((NTILE + MAIN_PER - 1) / MAIN_PER)   // 293

__global__ void __launch_bounds__(256, 2) main_mma(
    const float* __restrict__ ln_g, const float* __restrict__ ln_b,
    const float* __restrict__ bias, const float* __restrict__ W2,
    const float* __restrict__ b2,   float* __restrict__ out)
{
    extern __shared__ char smem[];
    const u32 sb   = smem_u32(smem);
    const int t    = threadIdx.x;
    const int wid  = t >> 5;
    const int lane = t & 31;

    float* b2s = (float*)(smem + SM_B2);
    uint2* Bhi = (uint2*)(smem + SM_BHI);
    uint2* Blo = (uint2*)(smem + SM_BLO);

    if (t < DD) b2s[t] = b2[t];

    for (int s = t; s < 4*8*32; s += 256) {
        const int ls = s & 31, nt = (s >> 5) & 7, ks = s >> 8;
        const int o  = nt*8 + (ls >> 2);
        const int d  = ks*16 + (ls & 3)*2;
        const float* w = W2 + (size_t)o*DD + d;
        float w0 = w[0], w1 = w[1], w8 = w[8], w9 = w[9];
        __nv_bfloat16 h0 = __float2bfloat16(w0), h1 = __float2bfloat16(w1);
        __nv_bfloat16 h8 = __float2bfloat16(w8), h9 = __float2bfloat16(w9);
        uint2 bh, bl;
        bh.x = ((u32)*(unsigned short*)&h0) | ((u32)*(unsigned short*)&h1 << 16);
        bh.y = ((u32)*(unsigned short*)&h8) | ((u32)*(unsigned short*)&h9 << 16);
        bl.x = bf2_u32(w0 - __bfloat162float(h0), w1 - __bfloat162float(h1));
        bl.y = bf2_u32(w8 - __bfloat162float(h8), w9 - __bfloat162float(h9));
        const int idx = (ks*8 + nt)*32 + ls;
        Bhi[idx] = bh;
        Blo[idx] = bl;
    }
    __syncthreads();

    const int d0 = 2*lane;
    const float lg0 = ln_g[d0], lg1 = ln_g[d0+1];
    const float lbn0 = ln_b[d0], lbn1 = ln_b[d0+1];
    const float bi0 = bias[d0], bi1 = bias[d0+1];

    const int arow = wid*16 + (lane & 15);
    const u32 a_off = (u32)arow*ASTRIDE + (u32)(lane >> 4)*16;
    const u32 ahi_base = sb + SM_AHI + a_off;
    const u32 alo_base = sb + SM_ALO + a_off;

    const int g  = lane >> 2;
    const int t4 = lane & 3;
    const int jl = wid*16 + (lane & 15);    // stats/S distribution row

    const int tile0 = blockIdx.x * MAIN_PER;
    const int tile1 = (tile0 + MAIN_PER < NTILE) ? (tile0 + MAIN_PER) : NTILE;

    int cur_bu = -1;
    float2 Bv[16];
    float  sb_part = 0.f;

    for (int tile = tile0; tile < tile1; tile++) {
        const int bu = tile >> 7;
        const int i  = tile & 127;
        const size_t row = (size_t)bu*RX + i;
        const float* st  = g_stats + (size_t)bu*RX*8;

        if (bu != cur_bu) {
            cur_bu = bu;
            const float* Bb = g_B + (size_t)bu*RX*DD;
            #pragma unroll
            for (int jo = 0; jo < 16; jo++)
                Bv[jo] = *(const float2*)(Bb + (size_t)(wid*16 + jo)*DD + d0);
            sb_part = st[jl*8 + 2 + (lane >> 4)];   // sumB / sumB2
        }

        const float2 P2  = *(const float2*)(g_P + row*DD + d0);
        const float2 G2  = *(const float2*)(g_G + row*DD + d0);
        const float2 spi = *(const float2*)(st + i*8);
        const float4 sdi = *(const float4*)(st + i*8 + 4);
        const float  S_part = g_S[row*RX + jl];

        __syncwarp();
        #pragma unroll
        for (int jo = 0; jo < 16; jo++) {
            const int j = wid*16 + jo;
            const float sumB  = __shfl_sync(0xffffffffu, sb_part, jo);
            const float sumB2 = __shfl_sync(0xffffffffu, sb_part, 16 + jo);
            const float Sij   = __shfl_sync(0xffffffffu, S_part, jo);
            float h0  = P2.x + Bv[jo].x;
            float h1  = P2.y + Bv[jo].y;
            float sum = spi.x + sumB;
            float e2  = spi.y + sumB2 + 2.f*Sij;
            const bool diag = (j == i);
            if (diag) {
                h0 += G2.x; h1 += G2.y;
                sum += sdi.x;
                e2  += sdi.y + 2.f*(sdi.z + sdi.w);
            }
            const float mu  = sum * (1.f/64.f);
            const float var = e2 * (1.f/64.f) - mu*mu;
            const float rs  = rsqrtf(var + 1e-5f);
            float y0 = fmaxf((h0 - mu)*rs*lg0 + lbn0, 0.f);
            float y1 = fmaxf((h1 - mu)*rs*lg1 + lbn1, 0.f);
            if (diag) { y0 += bi0; y1 += bi1; }

            __nv_bfloat16 hh0 = __float2bfloat16(y0);
            __nv_bfloat16 hh1 = __float2bfloat16(y1);
            u32 hiw = ((u32)*(unsigned short*)&hh0) | ((u32)*(unsigned short*)&hh1 << 16);
            u32 low = bf2_u32(y0 - __bfloat162float(hh0), y1 - __bfloat162float(hh1));
            const u32 boff = (u32)j*ASTRIDE + (u32)lane*4;
            *(u32*)(smem + SM_AHI + boff) = hiw;
            *(u32*)(smem + SM_ALO + boff) = low;
        }
        __syncwarp();

        u32 ah[4][4], al[4][4];
        #pragma unroll
        for (int ks = 0; ks < 4; ks++) {
            ldmat4(ah[ks], ahi_base + (u32)ks*32);
            ldmat4(al[ks], alo_base + (u32)ks*32);
        }
        __syncwarp();

        float* obase = out + row*RX*DD;
        #pragma unroll
        for (int nt = 0; nt < 8; nt++) {
            float c0 = 0.f, c1 = 0.f, c2 = 0.f, c3 = 0.f;
            #pragma unroll
            for (int ks = 0; ks < 4; ks++) {
                const int idx = (ks*8 + nt)*32 + lane;
                uint2 bh = Bhi[idx];
                uint2 bl = Blo[idx];
                mma_bf16(c0,c1,c2,c3, ah[ks][0],ah[ks][1],ah[ks][2],ah[ks][3], bh.x, bh.y);
                mma_bf16(c0,c1,c2,c3, ah[ks][0],ah[ks][1],ah[ks][2],ah[ks][3], bl.x, bl.y);
                mma_bf16(c0,c1,c2,c3, al[ks][0],al[ks][1],al[ks][2],al[ks][3], bh.x, bh.y);
            }
            const int o0 = nt*8 + t4*2;
            const float2 bb = *(const float2*)(b2s + o0);
            float2 v0; v0.x = c0 + bb.x; v0.y = c1 + bb.y;
            float2 v1; v1.x = c2 + bb.x; v1.y = c3 + bb.y;
            *(float2*)(obase + (size_t)(wid*16 + g)*DD + o0)     = v0;
            *(float2*)(obase + (size_t)(wid*16 + g + 8)*DD + o0) = v1;
        }
    }
}

// -------------------------------------------------------------------------
// Inputs (metadata order): x, W1, b1, ln_g, ln_b, bias, W2, b2
// -------------------------------------------------------------------------
extern "C" void kernel_launch(void* const* d_in, const int* in_sizes, int n_in,
                              void* d_out, int out_size)
{
    const float* x    = (const float*)d_in[0];
    const float* W1   = (const float*)d_in[1];
    const float* b1   = (const float*)d_in[2];
    const float* ln_g = (const float*)d_in[3];
    const float* ln_b = (const float*)d_in[4];
    const float* bias = (const float*)d_in[5];
    const float* W2   = (const float*)d_in[6];
    const float* b2   = (const float*)d_in[7];
    float* out = (float*)d_out;
    (void)in_sizes; (void)n_in; (void)out_size;

    cudaFuncSetAttribute(prep_kernel, cudaFuncAttributeMaxDynamicSharedMemorySize, PREP_SMEM_BYTES);
    cudaFuncSetAttribute(main_mma, cudaFuncAttributeMaxDynamicSharedMemorySize, SM_TOTAL);

    mean_kernel<<<NBU, 256>>>(x, W1, b1);
    prep_kernel<<<dim3(NBU, 8), 512, PREP_SMEM_BYTES>>>(x, W1);
    spb_kernel<<<dim3(NBU, 4), 256>>>();
    main_mma<<<MAIN_GRID, 256, SM_TOTAL>>>(ln_g, ln_b, bias, W2, b2, out);
}